// round 15
// baseline (speedup 1.0000x reference)
#include <cuda_runtime.h>
#include <math.h>

#define N_NODES 100000
#define N_EDGES 1600000
#define DIM 128
#define OUTC 16
#define WSTRIDE 130   // padded row stride for transposed W (LDS.64-aligned)
#define STAGE_CAP 2048

typedef unsigned long long ull;

// ---------------------------------------------------------------------------
// Scratch (__device__ globals: allocation-free rule)
// ---------------------------------------------------------------------------
__device__ float4 g_ht[(size_t)N_NODES * DIM / 4];   // gather output / z scratch
__device__ float4 g_h0[(size_t)N_NODES * DIM / 4];
__device__ float4 g_h1[(size_t)N_NODES * DIM / 4];
__device__ int    g_rowptr[N_NODES + 1];
__device__ int    g_wptr[N_NODES];
__device__ int    g_csrc[N_EDGES];
__device__ float  g_cw[N_EDGES];

// ---------------------------------------------------------------------------
// CSR build: zero counts -> histogram -> scan -> fill
// ---------------------------------------------------------------------------
__global__ void zero_counts_kernel(int* __restrict__ cnt) {
    int i = blockIdx.x * blockDim.x + threadIdx.x;
    if (i < N_NODES) cnt[i] = 0;
}

__global__ void hist_kernel(const int* __restrict__ dst, int* __restrict__ cnt) {
    int e = blockIdx.x * blockDim.x + threadIdx.x;
    if (e < N_EDGES) atomicAdd(&cnt[dst[e]], 1);
}

__global__ void scan_kernel(int* __restrict__ cnt_and_wptr,
                            int* __restrict__ rowptr) {
    __shared__ int ssum[1024];
    const int t = threadIdx.x;
    const int per = (N_NODES + 1023) / 1024;          // 98
    const int beg = t * per;
    const int end = (beg + per < N_NODES) ? beg + per : N_NODES;

    int local[104];
    int s = 0;
    for (int i = beg; i < end; i++) { local[i - beg] = cnt_and_wptr[i]; s += local[i - beg]; }
    const int mysum = s;
    ssum[t] = s;
    __syncthreads();

    for (int o = 1; o < 1024; o <<= 1) {
        int v = (t >= o) ? ssum[t - o] : 0;
        __syncthreads();
        ssum[t] += v;
        __syncthreads();
    }
    int off = ssum[t] - mysum;

    for (int i = beg; i < end; i++) {
        rowptr[i] = off;
        cnt_and_wptr[i] = off;
        off += local[i - beg];
    }
    if (t == 1023) rowptr[N_NODES] = N_EDGES;
}

__global__ void fill_kernel(const int* __restrict__ src,
                            const int* __restrict__ dst,
                            const float* __restrict__ ew,
                            int* __restrict__ wptr,
                            int* __restrict__ csrc,
                            float* __restrict__ cw) {
    int e = blockIdx.x * blockDim.x + threadIdx.x;
    if (e >= N_EDGES) return;
    int pos = atomicAdd(&wptr[dst[e]], 1);
    csrc[pos] = src[e];
    cw[pos]   = ew[e];
}

// ---------------------------------------------------------------------------
// Gather (128-dim): h[n] = (1+eps)*x[n] + sum w_e * x[src_e]
// Block of 8 warps = 8 nodes; indices staged in SMEM; 8-way unrolled row
// loads (MLP 8 per warp).
// ---------------------------------------------------------------------------
__global__ void __launch_bounds__(256)
gather_kernel(const float4* __restrict__ x4,
              const int* __restrict__ rowptr,
              const int* __restrict__ csrc,
              const float* __restrict__ cw,
              const float* __restrict__ eps,
              float4* __restrict__ h4) {
    __shared__ int   sIdx[STAGE_CAP];
    __shared__ float sW[STAGE_CAP];

    const int tid   = threadIdx.x;
    const int warp  = tid >> 5;
    const int lane  = tid & 31;
    const int node0 = blockIdx.x * 8;
    const int n     = node0 + warp;

    const int gbeg = rowptr[node0];
    const int gend = rowptr[node0 + 8];
    const int tot  = gend - gbeg;

    const int beg = rowptr[n];
    const int end = rowptr[n + 1];

    float4 a0 = make_float4(0.f, 0.f, 0.f, 0.f);
    float4 a1 = make_float4(0.f, 0.f, 0.f, 0.f);
    float4 a2 = make_float4(0.f, 0.f, 0.f, 0.f);
    float4 a3 = make_float4(0.f, 0.f, 0.f, 0.f);
    float4 a4 = make_float4(0.f, 0.f, 0.f, 0.f);
    float4 a5 = make_float4(0.f, 0.f, 0.f, 0.f);
    float4 a6 = make_float4(0.f, 0.f, 0.f, 0.f);
    float4 a7 = make_float4(0.f, 0.f, 0.f, 0.f);

    if (tot <= STAGE_CAP) {
        for (int i = tid; i < tot; i += 256) {
            sIdx[i] = csrc[gbeg + i];
            sW[i]   = cw[gbeg + i];
        }
        __syncthreads();

        const int rbeg = beg - gbeg;
        const int rend = end - gbeg;
        int i = rbeg;
        for (; i + 7 < rend; i += 8) {
            const int s0 = sIdx[i],     s1 = sIdx[i + 1];
            const int s2 = sIdx[i + 2], s3 = sIdx[i + 3];
            const int s4 = sIdx[i + 4], s5 = sIdx[i + 5];
            const int s6 = sIdx[i + 6], s7 = sIdx[i + 7];
            const float w0 = sW[i],     w1 = sW[i + 1];
            const float w2 = sW[i + 2], w3 = sW[i + 3];
            const float w4 = sW[i + 4], w5 = sW[i + 5];
            const float w6 = sW[i + 6], w7 = sW[i + 7];
            float4 v0 = x4[(size_t)s0 * (DIM / 4) + lane];
            float4 v1 = x4[(size_t)s1 * (DIM / 4) + lane];
            float4 v2 = x4[(size_t)s2 * (DIM / 4) + lane];
            float4 v3 = x4[(size_t)s3 * (DIM / 4) + lane];
            float4 v4 = x4[(size_t)s4 * (DIM / 4) + lane];
            float4 v5 = x4[(size_t)s5 * (DIM / 4) + lane];
            float4 v6 = x4[(size_t)s6 * (DIM / 4) + lane];
            float4 v7 = x4[(size_t)s7 * (DIM / 4) + lane];
            a0.x += w0 * v0.x; a0.y += w0 * v0.y; a0.z += w0 * v0.z; a0.w += w0 * v0.w;
            a1.x += w1 * v1.x; a1.y += w1 * v1.y; a1.z += w1 * v1.z; a1.w += w1 * v1.w;
            a2.x += w2 * v2.x; a2.y += w2 * v2.y; a2.z += w2 * v2.z; a2.w += w2 * v2.w;
            a3.x += w3 * v3.x; a3.y += w3 * v3.y; a3.z += w3 * v3.z; a3.w += w3 * v3.w;
            a4.x += w4 * v4.x; a4.y += w4 * v4.y; a4.z += w4 * v4.z; a4.w += w4 * v4.w;
            a5.x += w5 * v5.x; a5.y += w5 * v5.y; a5.z += w5 * v5.z; a5.w += w5 * v5.w;
            a6.x += w6 * v6.x; a6.y += w6 * v6.y; a6.z += w6 * v6.z; a6.w += w6 * v6.w;
            a7.x += w7 * v7.x; a7.y += w7 * v7.y; a7.z += w7 * v7.z; a7.w += w7 * v7.w;
        }
        for (; i + 3 < rend; i += 4) {
            const int s0 = sIdx[i],     s1 = sIdx[i + 1];
            const int s2 = sIdx[i + 2], s3 = sIdx[i + 3];
            const float w0 = sW[i],     w1 = sW[i + 1];
            const float w2 = sW[i + 2], w3 = sW[i + 3];
            float4 v0 = x4[(size_t)s0 * (DIM / 4) + lane];
            float4 v1 = x4[(size_t)s1 * (DIM / 4) + lane];
            float4 v2 = x4[(size_t)s2 * (DIM / 4) + lane];
            float4 v3 = x4[(size_t)s3 * (DIM / 4) + lane];
            a0.x += w0 * v0.x; a0.y += w0 * v0.y; a0.z += w0 * v0.z; a0.w += w0 * v0.w;
            a1.x += w1 * v1.x; a1.y += w1 * v1.y; a1.z += w1 * v1.z; a1.w += w1 * v1.w;
            a2.x += w2 * v2.x; a2.y += w2 * v2.y; a2.z += w2 * v2.z; a2.w += w2 * v2.w;
            a3.x += w3 * v3.x; a3.y += w3 * v3.y; a3.z += w3 * v3.z; a3.w += w3 * v3.w;
        }
        for (; i < rend; i++) {
            const int s0 = sIdx[i];
            const float w0 = sW[i];
            float4 v0 = x4[(size_t)s0 * (DIM / 4) + lane];
            a0.x += w0 * v0.x; a0.y += w0 * v0.y; a0.z += w0 * v0.z; a0.w += w0 * v0.w;
        }
    } else {
        // Fallback (statistically unreachable): direct gmem loop
        int i = beg;
        for (; i + 3 < end; i += 4) {
            const int s0 = csrc[i],     s1 = csrc[i + 1];
            const int s2 = csrc[i + 2], s3 = csrc[i + 3];
            const float w0 = cw[i],     w1 = cw[i + 1];
            const float w2 = cw[i + 2], w3 = cw[i + 3];
            float4 v0 = x4[(size_t)s0 * (DIM / 4) + lane];
            float4 v1 = x4[(size_t)s1 * (DIM / 4) + lane];
            float4 v2 = x4[(size_t)s2 * (DIM / 4) + lane];
            float4 v3 = x4[(size_t)s3 * (DIM / 4) + lane];
            a0.x += w0 * v0.x; a0.y += w0 * v0.y; a0.z += w0 * v0.z; a0.w += w0 * v0.w;
            a1.x += w1 * v1.x; a1.y += w1 * v1.y; a1.z += w1 * v1.z; a1.w += w1 * v1.w;
            a2.x += w2 * v2.x; a2.y += w2 * v2.y; a2.z += w2 * v2.z; a2.w += w2 * v2.w;
            a3.x += w3 * v3.x; a3.y += w3 * v3.y; a3.z += w3 * v3.z; a3.w += w3 * v3.w;
        }
        for (; i < end; i++) {
            const int s0 = csrc[i];
            const float w0 = cw[i];
            float4 v0 = x4[(size_t)s0 * (DIM / 4) + lane];
            a0.x += w0 * v0.x; a0.y += w0 * v0.y; a0.z += w0 * v0.z; a0.w += w0 * v0.w;
        }
    }

    const float ep = 1.0f + eps[0];
    float4 xv = x4[(size_t)n * (DIM / 4) + lane];
    float4 h;
    h.x = ep * xv.x + ((a0.x + a1.x) + (a2.x + a3.x)) + ((a4.x + a5.x) + (a6.x + a7.x));
    h.y = ep * xv.y + ((a0.y + a1.y) + (a2.y + a3.y)) + ((a4.y + a5.y) + (a6.y + a7.y));
    h.z = ep * xv.z + ((a0.z + a1.z) + (a2.z + a3.z)) + ((a4.z + a5.z) + (a6.z + a7.z));
    h.w = ep * xv.w + ((a0.w + a1.w) + (a2.w + a3.w)) + ((a4.w + a5.w) + (a6.w + a7.w));
    h4[(size_t)n * (DIM / 4) + lane] = h;
}

// ---------------------------------------------------------------------------
// GEMM + bias + relu + L2-normalize (FFMA2) with register-prefetch
// double-buffering of the h-tile.
// ---------------------------------------------------------------------------
__global__ void __launch_bounds__(128, 3)
gemm_norm_kernel(const float4* __restrict__ h4,
                 const float* __restrict__ W,
                 const float* __restrict__ b,
                 float4* __restrict__ out4) {
    extern __shared__ float sm[];
    float* sWT = sm;                        // 128 cols x WSTRIDE
    float* sH  = sm + DIM * WSTRIDE;        // 16 x 128 (i-major)
    float* sR  = sH + 16 * DIM;             // 64

    const int t    = threadIdx.x;
    const int lane = t & 31;
    const int warp = t >> 5;

    for (int i = t; i < DIM * DIM; i += 128) {
        const int k = i >> 7;
        const int c = i & 127;
        sWT[c * WSTRIDE + k] = W[i];
    }

    const float bias = b[t];
    const float* wrow = sWT + t * WSTRIDE;

    const int ntiles = N_NODES / 16;        // 6250
    const int stride = gridDim.x;

    int tile = blockIdx.x;
    if (tile >= ntiles) return;

    // Preload first tile into registers
    float4 r[4];
#pragma unroll
    for (int j = 0; j < 4; j++)
        r[j] = h4[(size_t)tile * (16 * DIM / 4) + t + j * 128];

    while (tile < ntiles) {
        const int n0 = tile * 16;
        __syncthreads();                    // sH free (prev tile's reads done)
#pragma unroll
        for (int j = 0; j < 4; j++)
            reinterpret_cast<float4*>(sH)[t + j * 128] = r[j];
        __syncthreads();

        // Prefetch next tile while computing this one
        const int next = tile + stride;
        if (next < ntiles) {
#pragma unroll
            for (int j = 0; j < 4; j++)
                r[j] = h4[(size_t)next * (16 * DIM / 4) + t + j * 128];
        }

        ull acc2[16];
#pragma unroll
        for (int i = 0; i < 16; i++) acc2[i] = 0ULL;

#pragma unroll 4
        for (int k = 0; k < DIM; k += 2) {
            const ull wp = *reinterpret_cast<const ull*>(wrow + k);
#pragma unroll
            for (int i = 0; i < 16; i++) {
                const ull hp = *reinterpret_cast<const ull*>(sH + i * DIM + k);
                asm("fma.rn.f32x2 %0, %1, %2, %0;"
                    : "+l"(acc2[i]) : "l"(hp), "l"(wp));
            }
        }

        float y[16];
#pragma unroll
        for (int i = 0; i < 16; i++) {
            const float lo = __uint_as_float((unsigned)(acc2[i] & 0xffffffffu));
            const float hi = __uint_as_float((unsigned)(acc2[i] >> 32));
            y[i] = fmaxf(lo + hi + bias, 0.f);
        }

#pragma unroll
        for (int i = 0; i < 16; i++) {
            float s = y[i] * y[i];
#pragma unroll
            for (int o = 16; o > 0; o >>= 1)
                s += __shfl_xor_sync(0xffffffffu, s, o);
            if (lane == 0) sR[warp * 16 + i] = s;
        }
        __syncthreads();

#pragma unroll
        for (int i = 0; i < 16; i++) {
            float ns  = sR[i] + sR[16 + i] + sR[32 + i] + sR[48 + i];
            float inv = 1.0f / fmaxf(sqrtf(ns), 1e-12f);
            reinterpret_cast<float*>(out4)[(size_t)(n0 + i) * DIM + t] = y[i] * inv;
        }
        tile = next;
    }
}

// ---------------------------------------------------------------------------
// z = h1 @ W2  (100k x 128 @ 128 x 16). One warp per node.
// ---------------------------------------------------------------------------
__global__ void __launch_bounds__(256)
zmat_kernel(const float4* __restrict__ h4,
            const float* __restrict__ W,
            float* __restrict__ z) {
    __shared__ alignas(16) float sWt[OUTC * DIM];   // sWt[j*128+k] = W[k][j]
    const int t = threadIdx.x;
    for (int i = t; i < OUTC * DIM; i += blockDim.x) {
        int j = i / DIM, k = i % DIM;
        sWt[i] = W[k * OUTC + j];
    }
    __syncthreads();

    const int wid  = (blockIdx.x * blockDim.x + t) >> 5;
    if (wid >= N_NODES) return;
    const int lane = t & 31;

    float4 h = h4[(size_t)wid * (DIM / 4) + lane];

    float v[OUTC];
#pragma unroll
    for (int j = 0; j < OUTC; j++) {
        float4 w4 = reinterpret_cast<float4*>(sWt + j * DIM)[lane];
        v[j] = h.x * w4.x + h.y * w4.y + h.z * w4.z + h.w * w4.w;
#pragma unroll
        for (int o = 16; o > 0; o >>= 1)
            v[j] += __shfl_xor_sync(0xffffffffu, v[j], o);
    }
    if (lane == 0) {
        float4* zp = reinterpret_cast<float4*>(z + (size_t)wid * OUTC);
#pragma unroll
        for (int q = 0; q < 4; q++)
            zp[q] = make_float4(v[q * 4], v[q * 4 + 1], v[q * 4 + 2], v[q * 4 + 3]);
    }
}

// ---------------------------------------------------------------------------
// Final gather in 16-dim z-space + bias + relu + softmax.
// Block of 8 warps = 8 nodes; indices staged in SMEM. Within a warp,
// lanes 0-15 process even edges, lanes 16-31 odd edges; halves combined
// with one shfl_xor(16).
// ---------------------------------------------------------------------------
__global__ void __launch_bounds__(256)
final_gather_kernel(const float* __restrict__ z,
                    const int* __restrict__ rowptr,
                    const int* __restrict__ csrc,
                    const float* __restrict__ b,
                    const float* __restrict__ eps,
                    float* __restrict__ logits,
                    float* __restrict__ probs) {
    __shared__ int sIdx[STAGE_CAP];

    const int tid   = threadIdx.x;
    const int warp  = tid >> 5;
    const int lane  = tid & 31;
    const int l16   = lane & 15;
    const int half  = lane >> 4;          // 0 or 1
    const int node0 = blockIdx.x * 8;
    const int n     = node0 + warp;

    const int gbeg = rowptr[node0];
    const int gend = rowptr[node0 + 8];
    const int tot  = gend - gbeg;

    const int beg = rowptr[n];
    const int end = rowptr[n + 1];

    float a0 = 0.f, a1 = 0.f, a2 = 0.f, a3 = 0.f;

    if (tot <= STAGE_CAP) {
        for (int i = tid; i < tot; i += 256)
            sIdx[i] = csrc[gbeg + i];
        __syncthreads();

        const int rbeg = beg - gbeg;
        const int rend = end - gbeg;
        // this half processes edges rbeg+half, rbeg+half+2, ...
        int i = rbeg + half;
        for (; i + 6 < rend; i += 8) {
            const int s0 = sIdx[i],     s1 = sIdx[i + 2];
            const int s2 = sIdx[i + 4], s3 = sIdx[i + 6];
            a0 += z[(size_t)s0 * OUTC + l16];
            a1 += z[(size_t)s1 * OUTC + l16];
            a2 += z[(size_t)s2 * OUTC + l16];
            a3 += z[(size_t)s3 * OUTC + l16];
        }
        for (; i < rend; i += 2)
            a0 += z[(size_t)sIdx[i] * OUTC + l16];
    } else {
        // Fallback: direct loop, split across halves
        int i = beg + half;
        for (; i < end; i += 2)
            a0 += z[(size_t)csrc[i] * OUTC + l16];
    }

    float a = (a0 + a1) + (a2 + a3);
    a += __shfl_xor_sync(0xffffffffu, a, 16);    // combine halves

    const float ep = 1.0f + eps[0];
    float v = ep * z[(size_t)n * OUTC + l16] + a + b[l16];
    v = fmaxf(v, 0.f);

    float mx = v;
#pragma unroll
    for (int o = 8; o > 0; o >>= 1)
        mx = fmaxf(mx, __shfl_xor_sync(0xffffffffu, mx, o));
    float ex = expf(v - mx);
    float se = ex;
#pragma unroll
    for (int o = 8; o > 0; o >>= 1)
        se += __shfl_xor_sync(0xffffffffu, se, o);

    if (lane < 16) {
        logits[(size_t)n * OUTC + l16] = v;
        probs [(size_t)n * OUTC + l16] = ex / se;
    }
}

// ---------------------------------------------------------------------------
// Launch — inputs bound by SIZE (permutation-proof).
// ---------------------------------------------------------------------------
extern "C" void kernel_launch(void* const* d_in, const int* in_sizes, int n_in,
                              void* d_out, int out_size) {
    const float* x  = nullptr;
    const int*   ei = nullptr;
    const float* ew = nullptr;
    const float* Wp[3] = {nullptr, nullptr, nullptr};
    const float* Bp[3] = {nullptr, nullptr, nullptr};
    const float* Ep[3] = {nullptr, nullptr, nullptr};
    int wi = 0, bi = 0, epi = 0;

    for (int i = 0; i < n_in; i++) {
        switch (in_sizes[i]) {
            case N_NODES * DIM: x  = (const float*)d_in[i]; break;
            case 2 * N_EDGES:   ei = (const int*)d_in[i];   break;
            case N_EDGES:       ew = (const float*)d_in[i]; break;
            case DIM * DIM:     if (wi < 2) Wp[wi++] = (const float*)d_in[i]; break;
            case DIM * OUTC:    Wp[2] = (const float*)d_in[i]; break;
            case DIM:           if (bi < 2) Bp[bi++] = (const float*)d_in[i]; break;
            case OUTC:          Bp[2] = (const float*)d_in[i]; break;
            case 1:             if (epi < 3) Ep[epi++] = (const float*)d_in[i]; break;
            default: break;
        }
    }

    float* out_logits = (float*)d_out;
    float* out_probs  = out_logits + (size_t)N_NODES * OUTC;

    float4 *ht, *h0, *h1;
    int *rowptr, *wptr, *csrc;
    float *cw;
    cudaGetSymbolAddress((void**)&ht,     g_ht);
    cudaGetSymbolAddress((void**)&h0,     g_h0);
    cudaGetSymbolAddress((void**)&h1,     g_h1);
    cudaGetSymbolAddress((void**)&rowptr, g_rowptr);
    cudaGetSymbolAddress((void**)&wptr,   g_wptr);
    cudaGetSymbolAddress((void**)&csrc,   g_csrc);
    cudaGetSymbolAddress((void**)&cw,     g_cw);

    const int* src = ei;             // row 0
    const int* dst = ei + N_EDGES;   // row 1

    const int smem = (DIM * WSTRIDE + 16 * DIM + 64) * sizeof(float);  // ~75 KB
    cudaFuncSetAttribute(gemm_norm_kernel,
                         cudaFuncAttributeMaxDynamicSharedMemorySize, smem);

    const float4* x4 = (const float4*)x;
    const int ngrid  = (N_NODES * 32 + 255) / 256;   // warp-per-node grids
    const int ggrid  = N_NODES / 8;                  // 12500 (8 nodes/block)

    // ---- CSR build (by destination), reused for all 3 layers ----
    zero_counts_kernel<<<(N_NODES + 255) / 256, 256>>>(wptr);
    hist_kernel<<<(N_EDGES + 255) / 256, 256>>>(dst, wptr);
    scan_kernel<<<1, 1024>>>(wptr, rowptr);
    fill_kernel<<<(N_EDGES + 255) / 256, 256>>>(src, dst, ew, wptr, csrc, cw);

    // ---- Layer 0 ----
    gather_kernel<<<ggrid, 256>>>(x4, rowptr, csrc, cw, Ep[0], ht);
    gemm_norm_kernel<<<444, 128, smem>>>(ht, Wp[0], Bp[0], h0);

    // ---- Layer 1 ----
    gather_kernel<<<ggrid, 256>>>(h0, rowptr, csrc, cw, Ep[1], ht);
    gemm_norm_kernel<<<444, 128, smem>>>(ht, Wp[1], Bp[1], h1);

    // ---- Layer 2: z = h1@W2, gather in 16-dim, softmax ----
    float* zbuf = (float*)ht;   // reuse scratch
    zmat_kernel<<<ngrid, 256>>>(h1, Wp[2], zbuf);
    final_gather_kernel<<<ggrid, 256>>>(zbuf, rowptr, csrc, Bp[2], Ep[2],
                                        out_logits, out_probs);
}

// round 16
// speedup vs baseline: 1.3091x; 1.3091x over previous
#include <cuda_runtime.h>
#include <math.h>

#define N_NODES 100000
#define N_EDGES 1600000
#define DIM 128
#define OUTC 16
#define STAGE_CAP 2048
#define HSTRIDE 132          // sH row stride (words): banks 4*gid+tig conflict-free
#define WSTR 136             // sW row stride (words): banks 8*tig+gid conflict-free

typedef unsigned long long ull;

// ---------------------------------------------------------------------------
// Scratch (__device__ globals: allocation-free rule)
// ---------------------------------------------------------------------------
__device__ float4 g_ht[(size_t)N_NODES * DIM / 4];   // gather output / z scratch
__device__ float4 g_h0[(size_t)N_NODES * DIM / 4];
__device__ float4 g_h1[(size_t)N_NODES * DIM / 4];
__device__ int    g_rowptr[N_NODES + 1];
__device__ int    g_wptr[N_NODES];
__device__ int    g_csrc[N_EDGES];
__device__ float  g_cw[N_EDGES];

__device__ __forceinline__ unsigned f2tf(float f) {
    unsigned r;
    asm("cvt.rna.tf32.f32 %0, %1;" : "=r"(r) : "f"(f));
    return r;
}

// ---------------------------------------------------------------------------
// CSR build: zero counts -> histogram -> scan -> fill
// ---------------------------------------------------------------------------
__global__ void zero_counts_kernel(int* __restrict__ cnt) {
    int i = blockIdx.x * blockDim.x + threadIdx.x;
    if (i < N_NODES) cnt[i] = 0;
}

__global__ void hist_kernel(const int* __restrict__ dst, int* __restrict__ cnt) {
    int e = blockIdx.x * blockDim.x + threadIdx.x;
    if (e < N_EDGES) atomicAdd(&cnt[dst[e]], 1);
}

__global__ void scan_kernel(int* __restrict__ cnt_and_wptr,
                            int* __restrict__ rowptr) {
    __shared__ int ssum[1024];
    const int t = threadIdx.x;
    const int per = (N_NODES + 1023) / 1024;          // 98
    const int beg = t * per;
    const int end = (beg + per < N_NODES) ? beg + per : N_NODES;

    int local[104];
    int s = 0;
    for (int i = beg; i < end; i++) { local[i - beg] = cnt_and_wptr[i]; s += local[i - beg]; }
    const int mysum = s;
    ssum[t] = s;
    __syncthreads();

    for (int o = 1; o < 1024; o <<= 1) {
        int v = (t >= o) ? ssum[t - o] : 0;
        __syncthreads();
        ssum[t] += v;
        __syncthreads();
    }
    int off = ssum[t] - mysum;

    for (int i = beg; i < end; i++) {
        rowptr[i] = off;
        cnt_and_wptr[i] = off;
        off += local[i - beg];
    }
    if (t == 1023) rowptr[N_NODES] = N_EDGES;
}

__global__ void fill_kernel(const int* __restrict__ src,
                            const int* __restrict__ dst,
                            const float* __restrict__ ew,
                            int* __restrict__ wptr,
                            int* __restrict__ csrc,
                            float* __restrict__ cw) {
    int e = blockIdx.x * blockDim.x + threadIdx.x;
    if (e >= N_EDGES) return;
    int pos = atomicAdd(&wptr[dst[e]], 1);
    csrc[pos] = src[e];
    cw[pos]   = ew[e];
}

// ---------------------------------------------------------------------------
// Gather (128-dim): h[n] = (1+eps)*x[n] + sum w_e * x[src_e]
// Block of 8 warps = 8 nodes; indices staged in SMEM; 4-way unrolled row
// loads (R14 form — best measured).
// ---------------------------------------------------------------------------
__global__ void __launch_bounds__(256)
gather_kernel(const float4* __restrict__ x4,
              const int* __restrict__ rowptr,
              const int* __restrict__ csrc,
              const float* __restrict__ cw,
              const float* __restrict__ eps,
              float4* __restrict__ h4) {
    __shared__ int   sIdx[STAGE_CAP];
    __shared__ float sW[STAGE_CAP];

    const int tid   = threadIdx.x;
    const int warp  = tid >> 5;
    const int lane  = tid & 31;
    const int node0 = blockIdx.x * 8;
    const int n     = node0 + warp;

    const int gbeg = rowptr[node0];
    const int gend = rowptr[node0 + 8];
    const int tot  = gend - gbeg;

    const int beg = rowptr[n];
    const int end = rowptr[n + 1];

    float4 a0 = make_float4(0.f, 0.f, 0.f, 0.f);
    float4 a1 = make_float4(0.f, 0.f, 0.f, 0.f);
    float4 a2 = make_float4(0.f, 0.f, 0.f, 0.f);
    float4 a3 = make_float4(0.f, 0.f, 0.f, 0.f);

    if (tot <= STAGE_CAP) {
        for (int i = tid; i < tot; i += 256) {
            sIdx[i] = csrc[gbeg + i];
            sW[i]   = cw[gbeg + i];
        }
        __syncthreads();

        const int rbeg = beg - gbeg;
        const int rend = end - gbeg;
        int i = rbeg;
        for (; i + 3 < rend; i += 4) {
            const int s0 = sIdx[i],     s1 = sIdx[i + 1];
            const int s2 = sIdx[i + 2], s3 = sIdx[i + 3];
            const float w0 = sW[i],     w1 = sW[i + 1];
            const float w2 = sW[i + 2], w3 = sW[i + 3];
            float4 v0 = x4[(size_t)s0 * (DIM / 4) + lane];
            float4 v1 = x4[(size_t)s1 * (DIM / 4) + lane];
            float4 v2 = x4[(size_t)s2 * (DIM / 4) + lane];
            float4 v3 = x4[(size_t)s3 * (DIM / 4) + lane];
            a0.x += w0 * v0.x; a0.y += w0 * v0.y; a0.z += w0 * v0.z; a0.w += w0 * v0.w;
            a1.x += w1 * v1.x; a1.y += w1 * v1.y; a1.z += w1 * v1.z; a1.w += w1 * v1.w;
            a2.x += w2 * v2.x; a2.y += w2 * v2.y; a2.z += w2 * v2.z; a2.w += w2 * v2.w;
            a3.x += w3 * v3.x; a3.y += w3 * v3.y; a3.z += w3 * v3.z; a3.w += w3 * v3.w;
        }
        for (; i < rend; i++) {
            const int s0 = sIdx[i];
            const float w0 = sW[i];
            float4 v0 = x4[(size_t)s0 * (DIM / 4) + lane];
            a0.x += w0 * v0.x; a0.y += w0 * v0.y; a0.z += w0 * v0.z; a0.w += w0 * v0.w;
        }
    } else {
        int i = beg;
        for (; i + 3 < end; i += 4) {
            const int s0 = csrc[i],     s1 = csrc[i + 1];
            const int s2 = csrc[i + 2], s3 = csrc[i + 3];
            const float w0 = cw[i],     w1 = cw[i + 1];
            const float w2 = cw[i + 2], w3 = cw[i + 3];
            float4 v0 = x4[(size_t)s0 * (DIM / 4) + lane];
            float4 v1 = x4[(size_t)s1 * (DIM / 4) + lane];
            float4 v2 = x4[(size_t)s2 * (DIM / 4) + lane];
            float4 v3 = x4[(size_t)s3 * (DIM / 4) + lane];
            a0.x += w0 * v0.x; a0.y += w0 * v0.y; a0.z += w0 * v0.z; a0.w += w0 * v0.w;
            a1.x += w1 * v1.x; a1.y += w1 * v1.y; a1.z += w1 * v1.z; a1.w += w1 * v1.w;
            a2.x += w2 * v2.x; a2.y += w2 * v2.y; a2.z += w2 * v2.z; a2.w += w2 * v2.w;
            a3.x += w3 * v3.x; a3.y += w3 * v3.y; a3.z += w3 * v3.z; a3.w += w3 * v3.w;
        }
        for (; i < end; i++) {
            const int s0 = csrc[i];
            const float w0 = cw[i];
            float4 v0 = x4[(size_t)s0 * (DIM / 4) + lane];
            a0.x += w0 * v0.x; a0.y += w0 * v0.y; a0.z += w0 * v0.z; a0.w += w0 * v0.w;
        }
    }

    const float ep = 1.0f + eps[0];
    float4 xv = x4[(size_t)n * (DIM / 4) + lane];
    float4 h;
    h.x = ep * xv.x + (a0.x + a1.x) + (a2.x + a3.x);
    h.y = ep * xv.y + (a0.y + a1.y) + (a2.y + a3.y);
    h.z = ep * xv.z + (a0.z + a1.z) + (a2.z + a3.z);
    h.w = ep * xv.w + (a0.w + a1.w) + (a2.w + a3.w);
    h4[(size_t)n * (DIM / 4) + lane] = h;
}

// ---------------------------------------------------------------------------
// GEMM via tf32 mma.sync.m16n8k8 + bias + relu + L2-normalize.
// Block = 128 thr (4 warps, 2x2): tile = 32 nodes x 128 cols.
// Warp (wr, wc): rows wr*16..+15, cols wc*64..+63 (8 n8 fragments).
// ---------------------------------------------------------------------------
__global__ void __launch_bounds__(128)
gemm_norm_tc(const float4* __restrict__ h4,
             const float* __restrict__ W,
             const float* __restrict__ b,
             float4* __restrict__ out4) {
    extern __shared__ float sm[];
    float* sW   = sm;                       // 128 rows x WSTR (tf32 bits)
    float* sH   = sm + DIM * WSTR;          // 32 rows x HSTRIDE (tf32 bits)
    float* sRed = sH + 32 * HSTRIDE;        // 2 x 32 row partial sums

    const int t    = threadIdx.x;
    const int warp = t >> 5;
    const int lane = t & 31;
    const int gid  = lane >> 2;             // 0..7
    const int tig  = lane & 3;              // 0..3
    const int wr   = warp >> 1;             // 0..1
    const int wc   = warp & 1;              // 0..1

    // Stage W as tf32: sW[k*WSTR + c]
    for (int i = t; i < DIM * DIM; i += 128) {
        const int k = i >> 7;
        const int c = i & 127;
        sW[k * WSTR + c] = __uint_as_float(f2tf(W[i]));
    }

    // Preload this thread's bias columns: col = wc*64 + nf*8 + tig*2 (+1)
    float bias0[8], bias1[8];
#pragma unroll
    for (int nf = 0; nf < 8; nf++) {
        const int col = wc * 64 + nf * 8 + tig * 2;
        bias0[nf] = b[col];
        bias1[nf] = b[col + 1];
    }

    const int arow0 = wr * 16 + gid;        // lower row of A frags
    const int ntiles = N_NODES / 32;        // 3125

    float* outf = reinterpret_cast<float*>(out4);

    for (int tile = blockIdx.x; tile < ntiles; tile += gridDim.x) {
        const int n0 = tile * 32;
        __syncthreads();                    // sH / sRed reusable

        // Stage h-tile as tf32: sH[row*HSTRIDE + c]
        for (int i = t; i < 32 * 32; i += 128) {
            const int row = i >> 5;
            const int c4  = i & 31;
            float4 v = h4[(size_t)(n0 + row) * 32 + c4];
            float4 o;
            o.x = __uint_as_float(f2tf(v.x));
            o.y = __uint_as_float(f2tf(v.y));
            o.z = __uint_as_float(f2tf(v.z));
            o.w = __uint_as_float(f2tf(v.w));
            *reinterpret_cast<float4*>(sH + row * HSTRIDE + c4 * 4) = o;
        }
        __syncthreads();

        float c[8][4];
#pragma unroll
        for (int nf = 0; nf < 8; nf++) {
            c[nf][0] = 0.f; c[nf][1] = 0.f; c[nf][2] = 0.f; c[nf][3] = 0.f;
        }

        for (int ks = 0; ks < DIM; ks += 8) {
            const unsigned a0 = __float_as_uint(sH[arow0 * HSTRIDE + ks + tig]);
            const unsigned a1 = __float_as_uint(sH[(arow0 + 8) * HSTRIDE + ks + tig]);
            const unsigned a2 = __float_as_uint(sH[arow0 * HSTRIDE + ks + tig + 4]);
            const unsigned a3 = __float_as_uint(sH[(arow0 + 8) * HSTRIDE + ks + tig + 4]);
#pragma unroll
            for (int nf = 0; nf < 8; nf++) {
                const int ncol = wc * 64 + nf * 8 + gid;
                const unsigned b0 = __float_as_uint(sW[(ks + tig) * WSTR + ncol]);
                const unsigned b1 = __float_as_uint(sW[(ks + tig + 4) * WSTR + ncol]);
                asm("mma.sync.aligned.m16n8k8.row.col.f32.tf32.tf32.f32 "
                    "{%0,%1,%2,%3}, {%4,%5,%6,%7}, {%8,%9}, {%0,%1,%2,%3};"
                    : "+f"(c[nf][0]), "+f"(c[nf][1]), "+f"(c[nf][2]), "+f"(c[nf][3])
                    : "r"(a0), "r"(a1), "r"(a2), "r"(a3), "r"(b0), "r"(b1));
            }
        }

        // bias + relu; per-row sum of squares
        float ss_lo = 0.f, ss_hi = 0.f;
#pragma unroll
        for (int nf = 0; nf < 8; nf++) {
            float y00 = fmaxf(c[nf][0] + bias0[nf], 0.f);
            float y01 = fmaxf(c[nf][1] + bias1[nf], 0.f);
            float y10 = fmaxf(c[nf][2] + bias0[nf], 0.f);
            float y11 = fmaxf(c[nf][3] + bias1[nf], 0.f);
            c[nf][0] = y00; c[nf][1] = y01; c[nf][2] = y10; c[nf][3] = y11;
            ss_lo += y00 * y00 + y01 * y01;
            ss_hi += y10 * y10 + y11 * y11;
        }
        // reduce across tig lanes (same row, different columns)
        ss_lo += __shfl_xor_sync(0xffffffffu, ss_lo, 1);
        ss_lo += __shfl_xor_sync(0xffffffffu, ss_lo, 2);
        ss_hi += __shfl_xor_sync(0xffffffffu, ss_hi, 1);
        ss_hi += __shfl_xor_sync(0xffffffffu, ss_hi, 2);

        if (tig == 0) {
            sRed[wc * 32 + arow0]     = ss_lo;
            sRed[wc * 32 + arow0 + 8] = ss_hi;
        }
        __syncthreads();

        const float ns_lo = sRed[arow0]     + sRed[32 + arow0];
        const float ns_hi = sRed[arow0 + 8] + sRed[32 + arow0 + 8];
        const float inv_lo = 1.0f / fmaxf(sqrtf(ns_lo), 1e-12f);
        const float inv_hi = 1.0f / fmaxf(sqrtf(ns_hi), 1e-12f);

#pragma unroll
        for (int nf = 0; nf < 8; nf++) {
            const int col = wc * 64 + nf * 8 + tig * 2;
            float2 lo = make_float2(c[nf][0] * inv_lo, c[nf][1] * inv_lo);
            float2 hi = make_float2(c[nf][2] * inv_hi, c[nf][3] * inv_hi);
            *reinterpret_cast<float2*>(outf + (size_t)(n0 + arow0) * DIM + col)     = lo;
            *reinterpret_cast<float2*>(outf + (size_t)(n0 + arow0 + 8) * DIM + col) = hi;
        }
    }
}

// ---------------------------------------------------------------------------
// z = h1 @ W2  (100k x 128 @ 128 x 16). One warp per node.
// ---------------------------------------------------------------------------
__global__ void __launch_bounds__(256)
zmat_kernel(const float4* __restrict__ h4,
            const float* __restrict__ W,
            float* __restrict__ z) {
    __shared__ alignas(16) float sWt[OUTC * DIM];   // sWt[j*128+k] = W[k][j]
    const int t = threadIdx.x;
    for (int i = t; i < OUTC * DIM; i += blockDim.x) {
        int j = i / DIM, k = i % DIM;
        sWt[i] = W[k * OUTC + j];
    }
    __syncthreads();

    const int wid  = (blockIdx.x * blockDim.x + t) >> 5;
    if (wid >= N_NODES) return;
    const int lane = t & 31;

    float4 h = h4[(size_t)wid * (DIM / 4) + lane];

    float v[OUTC];
#pragma unroll
    for (int j = 0; j < OUTC; j++) {
        float4 w4 = reinterpret_cast<float4*>(sWt + j * DIM)[lane];
        v[j] = h.x * w4.x + h.y * w4.y + h.z * w4.z + h.w * w4.w;
#pragma unroll
        for (int o = 16; o > 0; o >>= 1)
            v[j] += __shfl_xor_sync(0xffffffffu, v[j], o);
    }
    if (lane == 0) {
        float4* zp = reinterpret_cast<float4*>(z + (size_t)wid * OUTC);
#pragma unroll
        for (int q = 0; q < 4; q++)
            zp[q] = make_float4(v[q * 4], v[q * 4 + 1], v[q * 4 + 2], v[q * 4 + 3]);
    }
}

// ---------------------------------------------------------------------------
// Final gather in 16-dim z-space + bias + relu + softmax. One warp per node.
// ---------------------------------------------------------------------------
__global__ void __launch_bounds__(256)
final_gather_kernel(const float* __restrict__ z,
                    const int* __restrict__ rowptr,
                    const int* __restrict__ csrc,
                    const float* __restrict__ b,
                    const float* __restrict__ eps,
                    float* __restrict__ logits,
                    float* __restrict__ probs) {
    const int wid  = (blockIdx.x * blockDim.x + threadIdx.x) >> 5;
    if (wid >= N_NODES) return;
    const int lane = threadIdx.x & 31;
    const int l16  = lane & 15;

    const int beg = rowptr[wid];
    const int end = rowptr[wid + 1];

    float a0 = 0.f, a1 = 0.f, a2 = 0.f, a3 = 0.f;
    int i = beg;
    for (; i + 3 < end; i += 4) {
        const int s0 = csrc[i],     s1 = csrc[i + 1];
        const int s2 = csrc[i + 2], s3 = csrc[i + 3];
        a0 += z[(size_t)s0 * OUTC + l16];
        a1 += z[(size_t)s1 * OUTC + l16];
        a2 += z[(size_t)s2 * OUTC + l16];
        a3 += z[(size_t)s3 * OUTC + l16];
    }
    for (; i < end; i++)
        a0 += z[(size_t)csrc[i] * OUTC + l16];

    const float ep = 1.0f + eps[0];
    float v = ep * z[(size_t)wid * OUTC + l16] + a0 + a1 + a2 + a3 + b[l16];
    v = fmaxf(v, 0.f);

    float mx = v;
#pragma unroll
    for (int o = 8; o > 0; o >>= 1)
        mx = fmaxf(mx, __shfl_xor_sync(0xffffffffu, mx, o));
    float ex = expf(v - mx);
    float se = ex;
#pragma unroll
    for (int o = 8; o > 0; o >>= 1)
        se += __shfl_xor_sync(0xffffffffu, se, o);

    if (lane < 16) {
        logits[(size_t)wid * OUTC + l16] = v;
        probs [(size_t)wid * OUTC + l16] = ex / se;
    }
}

// ---------------------------------------------------------------------------
// Launch — inputs bound by SIZE (permutation-proof).
// ---------------------------------------------------------------------------
extern "C" void kernel_launch(void* const* d_in, const int* in_sizes, int n_in,
                              void* d_out, int out_size) {
    const float* x  = nullptr;
    const int*   ei = nullptr;
    const float* ew = nullptr;
    const float* Wp[3] = {nullptr, nullptr, nullptr};
    const float* Bp[3] = {nullptr, nullptr, nullptr};
    const float* Ep[3] = {nullptr, nullptr, nullptr};
    int wi = 0, bi = 0, epi = 0;

    for (int i = 0; i < n_in; i++) {
        switch (in_sizes[i]) {
            case N_NODES * DIM: x  = (const float*)d_in[i]; break;
            case 2 * N_EDGES:   ei = (const int*)d_in[i];   break;
            case N_EDGES:       ew = (const float*)d_in[i]; break;
            case DIM * DIM:     if (wi < 2) Wp[wi++] = (const float*)d_in[i]; break;
            case DIM * OUTC:    Wp[2] = (const float*)d_in[i]; break;
            case DIM:           if (bi < 2) Bp[bi++] = (const float*)d_in[i]; break;
            case OUTC:          Bp[2] = (const float*)d_in[i]; break;
            case 1:             if (epi < 3) Ep[epi++] = (const float*)d_in[i]; break;
            default: break;
        }
    }

    float* out_logits = (float*)d_out;
    float* out_probs  = out_logits + (size_t)N_NODES * OUTC;

    float4 *ht, *h0, *h1;
    int *rowptr, *wptr, *csrc;
    float *cw;
    cudaGetSymbolAddress((void**)&ht,     g_ht);
    cudaGetSymbolAddress((void**)&h0,     g_h0);
    cudaGetSymbolAddress((void**)&h1,     g_h1);
    cudaGetSymbolAddress((void**)&rowptr, g_rowptr);
    cudaGetSymbolAddress((void**)&wptr,   g_wptr);
    cudaGetSymbolAddress((void**)&csrc,   g_csrc);
    cudaGetSymbolAddress((void**)&cw,     g_cw);

    const int* src = ei;             // row 0
    const int* dst = ei + N_EDGES;   // row 1

    const int smem_tc = (DIM * WSTR + 32 * HSTRIDE + 64) * sizeof(float);  // ~87 KB
    cudaFuncSetAttribute(gemm_norm_tc,
                         cudaFuncAttributeMaxDynamicSharedMemorySize, smem_tc);

    const float4* x4 = (const float4*)x;
    const int ngrid  = (N_NODES * 32 + 255) / 256;   // warp-per-node grids
    const int ggrid  = N_NODES / 8;                  // 12500 (8 nodes/block)

    // ---- CSR build (by destination), reused for all 3 layers ----
    zero_counts_kernel<<<(N_NODES + 255) / 256, 256>>>(wptr);
    hist_kernel<<<(N_EDGES + 255) / 256, 256>>>(dst, wptr);
    scan_kernel<<<1, 1024>>>(wptr, rowptr);
    fill_kernel<<<(N_EDGES + 255) / 256, 256>>>(src, dst, ew, wptr, csrc, cw);

    // ---- Layer 0 ----
    gather_kernel<<<ggrid, 256>>>(x4, rowptr, csrc, cw, Ep[0], ht);
    gemm_norm_tc<<<296, 128, smem_tc>>>(ht, Wp[0], Bp[0], h0);

    // ---- Layer 1 ----
    gather_kernel<<<ggrid, 256>>>(h0, rowptr, csrc, cw, Ep[1], ht);
    gemm_norm_tc<<<296, 128, smem_tc>>>(ht, Wp[1], Bp[1], h1);

    // ---- Layer 2: z = h1@W2, gather in 16-dim, softmax ----
    float* zbuf = (float*)ht;   // reuse scratch
    zmat_kernel<<<ngrid, 256>>>(h1, Wp[2], zbuf);
    final_gather_kernel<<<ngrid, 256>>>(zbuf, rowptr, csrc, Bp[2], Ep[2],
                                        out_logits, out_probs);
}

// round 17
// speedup vs baseline: 1.3431x; 1.0260x over previous
#include <cuda_runtime.h>
#include <cuda_fp16.h>
#include <math.h>

#define N_NODES 100000
#define N_EDGES 1600000
#define DIM 128
#define OUTC 16
#define STAGE_CAP 2048
#define HSTRIDE 132          // sH row stride (words)
#define WSTR 136             // sW row stride (words)

typedef unsigned long long ull;

// ---------------------------------------------------------------------------
// Scratch (__device__ globals: allocation-free rule)
// ---------------------------------------------------------------------------
__device__ uint2  g_xh [(size_t)N_NODES * DIM / 4];  // fp16 x / later z scratch
__device__ uint2  g_hth[(size_t)N_NODES * DIM / 4];  // fp16 gather output
__device__ uint2  g_h0h[(size_t)N_NODES * DIM / 4];  // fp16 layer-0 output
__device__ float4 g_h1 [(size_t)N_NODES * DIM / 4];  // fp32 layer-1 output
__device__ int    g_rowptr[N_NODES + 1];
__device__ int    g_wptr[N_NODES];
__device__ int    g_csrc[N_EDGES];
__device__ float  g_cw[N_EDGES];

__device__ __forceinline__ unsigned f2tf(float f) {
    unsigned r;
    asm("cvt.rna.tf32.f32 %0, %1;" : "=r"(r) : "f"(f));
    return r;
}

// ---------------------------------------------------------------------------
// CSR build: zero counts -> histogram -> scan -> fill
// ---------------------------------------------------------------------------
__global__ void zero_counts_kernel(int* __restrict__ cnt) {
    int i = blockIdx.x * blockDim.x + threadIdx.x;
    if (i < N_NODES) cnt[i] = 0;
}

__global__ void hist_kernel(const int* __restrict__ dst, int* __restrict__ cnt) {
    int e = blockIdx.x * blockDim.x + threadIdx.x;
    if (e < N_EDGES) atomicAdd(&cnt[dst[e]], 1);
}

__global__ void scan_kernel(int* __restrict__ cnt_and_wptr,
                            int* __restrict__ rowptr) {
    __shared__ int ssum[1024];
    const int t = threadIdx.x;
    const int per = (N_NODES + 1023) / 1024;          // 98
    const int beg = t * per;
    const int end = (beg + per < N_NODES) ? beg + per : N_NODES;

    int local[104];
    int s = 0;
    for (int i = beg; i < end; i++) { local[i - beg] = cnt_and_wptr[i]; s += local[i - beg]; }
    const int mysum = s;
    ssum[t] = s;
    __syncthreads();

    for (int o = 1; o < 1024; o <<= 1) {
        int v = (t >= o) ? ssum[t - o] : 0;
        __syncthreads();
        ssum[t] += v;
        __syncthreads();
    }
    int off = ssum[t] - mysum;

    for (int i = beg; i < end; i++) {
        rowptr[i] = off;
        cnt_and_wptr[i] = off;
        off += local[i - beg];
    }
    if (t == 1023) rowptr[N_NODES] = N_EDGES;
}

__global__ void fill_kernel(const int* __restrict__ src,
                            const int* __restrict__ dst,
                            const float* __restrict__ ew,
                            int* __restrict__ wptr,
                            int* __restrict__ csrc,
                            float* __restrict__ cw) {
    int e = blockIdx.x * blockDim.x + threadIdx.x;
    if (e >= N_EDGES) return;
    int pos = atomicAdd(&wptr[dst[e]], 1);
    csrc[pos] = src[e];
    cw[pos]   = ew[e];
}

// ---------------------------------------------------------------------------
// fp32 -> fp16 convert (4 elements per thread, grid-stride)
// ---------------------------------------------------------------------------
__global__ void convert_kernel(const float4* __restrict__ in,
                               uint2* __restrict__ out, int n4) {
    for (int i = blockIdx.x * blockDim.x + threadIdx.x; i < n4;
         i += gridDim.x * blockDim.x) {
        float4 v = in[i];
        __half2 lo = __floats2half2_rn(v.x, v.y);
        __half2 hi = __floats2half2_rn(v.z, v.w);
        uint2 r;
        r.x = *reinterpret_cast<unsigned*>(&lo);
        r.y = *reinterpret_cast<unsigned*>(&hi);
        out[i] = r;
    }
}

// ---------------------------------------------------------------------------
// Gather (128-dim, fp16 in / fp16 out): h[n] = (1+eps)*x[n] + sum w_e*x[src_e]
// Block of 8 warps = 8 nodes; indices staged in SMEM; 4-way unrolled row
// loads. Rows are 256 B (uint2 per lane); accumulation in fp32.
// ---------------------------------------------------------------------------
__global__ void __launch_bounds__(256)
gather_kernel(const uint2* __restrict__ xh,
              const int* __restrict__ rowptr,
              const int* __restrict__ csrc,
              const float* __restrict__ cw,
              const float* __restrict__ eps,
              uint2* __restrict__ outh) {
    __shared__ int   sIdx[STAGE_CAP];
    __shared__ float sW[STAGE_CAP];

    const int tid   = threadIdx.x;
    const int warp  = tid >> 5;
    const int lane  = tid & 31;
    const int node0 = blockIdx.x * 8;
    const int n     = node0 + warp;

    const int gbeg = rowptr[node0];
    const int gend = rowptr[node0 + 8];
    const int tot  = gend - gbeg;

    const int beg = rowptr[n];
    const int end = rowptr[n + 1];

    float4 a0 = make_float4(0.f, 0.f, 0.f, 0.f);
    float4 a1 = make_float4(0.f, 0.f, 0.f, 0.f);
    float4 a2 = make_float4(0.f, 0.f, 0.f, 0.f);
    float4 a3 = make_float4(0.f, 0.f, 0.f, 0.f);

#define ACC_H(ACC, R, WGT) do {                                              \
        float2 _p = __half22float2(*reinterpret_cast<__half2*>(&(R).x));     \
        float2 _q = __half22float2(*reinterpret_cast<__half2*>(&(R).y));     \
        (ACC).x += (WGT) * _p.x; (ACC).y += (WGT) * _p.y;                    \
        (ACC).z += (WGT) * _q.x; (ACC).w += (WGT) * _q.y;                    \
    } while (0)

    if (tot <= STAGE_CAP) {
        for (int i = tid; i < tot; i += 256) {
            sIdx[i] = csrc[gbeg + i];
            sW[i]   = cw[gbeg + i];
        }
        __syncthreads();

        const int rbeg = beg - gbeg;
        const int rend = end - gbeg;
        int i = rbeg;
        for (; i + 3 < rend; i += 4) {
            const int s0 = sIdx[i],     s1 = sIdx[i + 1];
            const int s2 = sIdx[i + 2], s3 = sIdx[i + 3];
            const float w0 = sW[i],     w1 = sW[i + 1];
            const float w2 = sW[i + 2], w3 = sW[i + 3];
            uint2 r0 = xh[(size_t)s0 * 32 + lane];
            uint2 r1 = xh[(size_t)s1 * 32 + lane];
            uint2 r2 = xh[(size_t)s2 * 32 + lane];
            uint2 r3 = xh[(size_t)s3 * 32 + lane];
            ACC_H(a0, r0, w0);
            ACC_H(a1, r1, w1);
            ACC_H(a2, r2, w2);
            ACC_H(a3, r3, w3);
        }
        for (; i < rend; i++) {
            const int s0 = sIdx[i];
            const float w0 = sW[i];
            uint2 r0 = xh[(size_t)s0 * 32 + lane];
            ACC_H(a0, r0, w0);
        }
    } else {
        int i = beg;
        for (; i + 3 < end; i += 4) {
            const int s0 = csrc[i],     s1 = csrc[i + 1];
            const int s2 = csrc[i + 2], s3 = csrc[i + 3];
            const float w0 = cw[i],     w1 = cw[i + 1];
            const float w2 = cw[i + 2], w3 = cw[i + 3];
            uint2 r0 = xh[(size_t)s0 * 32 + lane];
            uint2 r1 = xh[(size_t)s1 * 32 + lane];
            uint2 r2 = xh[(size_t)s2 * 32 + lane];
            uint2 r3 = xh[(size_t)s3 * 32 + lane];
            ACC_H(a0, r0, w0);
            ACC_H(a1, r1, w1);
            ACC_H(a2, r2, w2);
            ACC_H(a3, r3, w3);
        }
        for (; i < end; i++) {
            const int s0 = csrc[i];
            const float w0 = cw[i];
            uint2 r0 = xh[(size_t)s0 * 32 + lane];
            ACC_H(a0, r0, w0);
        }
    }
#undef ACC_H

    const float ep = 1.0f + eps[0];
    uint2 rs = xh[(size_t)n * 32 + lane];
    float2 sp = __half22float2(*reinterpret_cast<__half2*>(&rs.x));
    float2 sq = __half22float2(*reinterpret_cast<__half2*>(&rs.y));
    float4 h;
    h.x = ep * sp.x + (a0.x + a1.x) + (a2.x + a3.x);
    h.y = ep * sp.y + (a0.y + a1.y) + (a2.y + a3.y);
    h.z = ep * sq.x + (a0.z + a1.z) + (a2.z + a3.z);
    h.w = ep * sq.y + (a0.w + a1.w) + (a2.w + a3.w);

    __half2 lo = __floats2half2_rn(h.x, h.y);
    __half2 hi = __floats2half2_rn(h.z, h.w);
    uint2 o;
    o.x = *reinterpret_cast<unsigned*>(&lo);
    o.y = *reinterpret_cast<unsigned*>(&hi);
    outh[(size_t)n * 32 + lane] = o;
}

// ---------------------------------------------------------------------------
// GEMM via tf32 mma.sync.m16n8k8 + bias + relu + L2-normalize.
// Input h is fp16 (exact in tf32). Outputs: optional fp32 (out4) and/or
// optional fp16 (outh) per flags.
// ---------------------------------------------------------------------------
__global__ void __launch_bounds__(128)
gemm_norm_tc(const uint2* __restrict__ hth,
             const float* __restrict__ W,
             const float* __restrict__ b,
             float4* __restrict__ out4,
             __half* __restrict__ outh,
             int wf32, int wf16) {
    extern __shared__ float sm[];
    float* sW   = sm;                       // 128 rows x WSTR (tf32 bits)
    float* sH   = sm + DIM * WSTR;          // 32 rows x HSTRIDE
    float* sRed = sH + 32 * HSTRIDE;        // 2 x 32 row partial sums

    const int t    = threadIdx.x;
    const int warp = t >> 5;
    const int lane = t & 31;
    const int gid  = lane >> 2;             // 0..7
    const int tig  = lane & 3;              // 0..3
    const int wr   = warp >> 1;             // 0..1
    const int wc   = warp & 1;              // 0..1

    for (int i = t; i < DIM * DIM; i += 128) {
        const int k = i >> 7;
        const int c = i & 127;
        sW[k * WSTR + c] = __uint_as_float(f2tf(W[i]));
    }

    float bias0[8], bias1[8];
#pragma unroll
    for (int nf = 0; nf < 8; nf++) {
        const int col = wc * 64 + nf * 8 + tig * 2;
        bias0[nf] = b[col];
        bias1[nf] = b[col + 1];
    }

    const int arow0 = wr * 16 + gid;
    const int ntiles = N_NODES / 32;        // 3125

    float* outf = reinterpret_cast<float*>(out4);

    for (int tile = blockIdx.x; tile < ntiles; tile += gridDim.x) {
        const int n0 = tile * 32;
        __syncthreads();

        // Stage h-tile (fp16 -> fp32, exact in tf32)
        for (int i = t; i < 32 * 32; i += 128) {
            const int row = i >> 5;
            const int c4  = i & 31;
            uint2 v = hth[(size_t)(n0 + row) * 32 + c4];
            float2 p = __half22float2(*reinterpret_cast<__half2*>(&v.x));
            float2 q = __half22float2(*reinterpret_cast<__half2*>(&v.y));
            float4 o = make_float4(p.x, p.y, q.x, q.y);
            *reinterpret_cast<float4*>(sH + row * HSTRIDE + c4 * 4) = o;
        }
        __syncthreads();

        float c[8][4];
#pragma unroll
        for (int nf = 0; nf < 8; nf++) {
            c[nf][0] = 0.f; c[nf][1] = 0.f; c[nf][2] = 0.f; c[nf][3] = 0.f;
        }

        for (int ks = 0; ks < DIM; ks += 8) {
            const unsigned a0 = __float_as_uint(sH[arow0 * HSTRIDE + ks + tig]);
            const unsigned a1 = __float_as_uint(sH[(arow0 + 8) * HSTRIDE + ks + tig]);
            const unsigned a2 = __float_as_uint(sH[arow0 * HSTRIDE + ks + tig + 4]);
            const unsigned a3 = __float_as_uint(sH[(arow0 + 8) * HSTRIDE + ks + tig + 4]);
#pragma unroll
            for (int nf = 0; nf < 8; nf++) {
                const int ncol = wc * 64 + nf * 8 + gid;
                const unsigned b0 = __float_as_uint(sW[(ks + tig) * WSTR + ncol]);
                const unsigned b1 = __float_as_uint(sW[(ks + tig + 4) * WSTR + ncol]);
                asm("mma.sync.aligned.m16n8k8.row.col.f32.tf32.tf32.f32 "
                    "{%0,%1,%2,%3}, {%4,%5,%6,%7}, {%8,%9}, {%0,%1,%2,%3};"
                    : "+f"(c[nf][0]), "+f"(c[nf][1]), "+f"(c[nf][2]), "+f"(c[nf][3])
                    : "r"(a0), "r"(a1), "r"(a2), "r"(a3), "r"(b0), "r"(b1));
            }
        }

        float ss_lo = 0.f, ss_hi = 0.f;
#pragma unroll
        for (int nf = 0; nf < 8; nf++) {
            float y00 = fmaxf(c[nf][0] + bias0[nf], 0.f);
            float y01 = fmaxf(c[nf][1] + bias1[nf], 0.f);
            float y10 = fmaxf(c[nf][2] + bias0[nf], 0.f);
            float y11 = fmaxf(c[nf][3] + bias1[nf], 0.f);
            c[nf][0] = y00; c[nf][1] = y01; c[nf][2] = y10; c[nf][3] = y11;
            ss_lo += y00 * y00 + y01 * y01;
            ss_hi += y10 * y10 + y11 * y11;
        }
        ss_lo += __shfl_xor_sync(0xffffffffu, ss_lo, 1);
        ss_lo += __shfl_xor_sync(0xffffffffu, ss_lo, 2);
        ss_hi += __shfl_xor_sync(0xffffffffu, ss_hi, 1);
        ss_hi += __shfl_xor_sync(0xffffffffu, ss_hi, 2);

        if (tig == 0) {
            sRed[wc * 32 + arow0]     = ss_lo;
            sRed[wc * 32 + arow0 + 8] = ss_hi;
        }
        __syncthreads();

        const float ns_lo = sRed[arow0]     + sRed[32 + arow0];
        const float ns_hi = sRed[arow0 + 8] + sRed[32 + arow0 + 8];
        const float inv_lo = 1.0f / fmaxf(sqrtf(ns_lo), 1e-12f);
        const float inv_hi = 1.0f / fmaxf(sqrtf(ns_hi), 1e-12f);

#pragma unroll
        for (int nf = 0; nf < 8; nf++) {
            const int col = wc * 64 + nf * 8 + tig * 2;
            const float v00 = c[nf][0] * inv_lo, v01 = c[nf][1] * inv_lo;
            const float v10 = c[nf][2] * inv_hi, v11 = c[nf][3] * inv_hi;
            if (wf32) {
                *reinterpret_cast<float2*>(outf + (size_t)(n0 + arow0) * DIM + col)
                    = make_float2(v00, v01);
                *reinterpret_cast<float2*>(outf + (size_t)(n0 + arow0 + 8) * DIM + col)
                    = make_float2(v10, v11);
            }
            if (wf16) {
                *reinterpret_cast<__half2*>(outh + (size_t)(n0 + arow0) * DIM + col)
                    = __floats2half2_rn(v00, v01);
                *reinterpret_cast<__half2*>(outh + (size_t)(n0 + arow0 + 8) * DIM + col)
                    = __floats2half2_rn(v10, v11);
            }
        }
    }
}

// ---------------------------------------------------------------------------
// z = h1 @ W2  (100k x 128 @ 128 x 16). One warp per node. h1 fp32.
// ---------------------------------------------------------------------------
__global__ void __launch_bounds__(256)
zmat_kernel(const float4* __restrict__ h4,
            const float* __restrict__ W,
            float* __restrict__ z) {
    __shared__ alignas(16) float sWt[OUTC * DIM];   // sWt[j*128+k] = W[k][j]
    const int t = threadIdx.x;
    for (int i = t; i < OUTC * DIM; i += blockDim.x) {
        int j = i / DIM, k = i % DIM;
        sWt[i] = W[k * OUTC + j];
    }
    __syncthreads();

    const int wid  = (blockIdx.x * blockDim.x + t) >> 5;
    if (wid >= N_NODES) return;
    const int lane = t & 31;

    float4 h = h4[(size_t)wid * (DIM / 4) + lane];

    float v[OUTC];
#pragma unroll
    for (int j = 0; j < OUTC; j++) {
        float4 w4 = reinterpret_cast<float4*>(sWt + j * DIM)[lane];
        v[j] = h.x * w4.x + h.y * w4.y + h.z * w4.z + h.w * w4.w;
#pragma unroll
        for (int o = 16; o > 0; o >>= 1)
            v[j] += __shfl_xor_sync(0xffffffffu, v[j], o);
    }
    if (lane == 0) {
        float4* zp = reinterpret_cast<float4*>(z + (size_t)wid * OUTC);
#pragma unroll
        for (int q = 0; q < 4; q++)
            zp[q] = make_float4(v[q * 4], v[q * 4 + 1], v[q * 4 + 2], v[q * 4 + 3]);
    }
}

// ---------------------------------------------------------------------------
// Final gather in 16-dim z-space + bias + relu + softmax. One warp per node.
// ---------------------------------------------------------------------------
__global__ void __launch_bounds__(256)
final_gather_kernel(const float* __restrict__ z,
                    const int* __restrict__ rowptr,
                    const int* __restrict__ csrc,
                    const float* __restrict__ b,
                    const float* __restrict__ eps,
                    float* __restrict__ logits,
                    float* __restrict__ probs) {
    const int wid  = (blockIdx.x * blockDim.x + threadIdx.x) >> 5;
    if (wid >= N_NODES) return;
    const int lane = threadIdx.x & 31;
    const int l16  = lane & 15;

    const int beg = rowptr[wid];
    const int end = rowptr[wid + 1];

    float a0 = 0.f, a1 = 0.f, a2 = 0.f, a3 = 0.f;
    int i = beg;
    for (; i + 3 < end; i += 4) {
        const int s0 = csrc[i],     s1 = csrc[i + 1];
        const int s2 = csrc[i + 2], s3 = csrc[i + 3];
        a0 += z[(size_t)s0 * OUTC + l16];
        a1 += z[(size_t)s1 * OUTC + l16];
        a2 += z[(size_t)s2 * OUTC + l16];
        a3 += z[(size_t)s3 * OUTC + l16];
    }
    for (; i < end; i++)
        a0 += z[(size_t)csrc[i] * OUTC + l16];

    const float ep = 1.0f + eps[0];
    float v = ep * z[(size_t)wid * OUTC + l16] + a0 + a1 + a2 + a3 + b[l16];
    v = fmaxf(v, 0.f);

    float mx = v;
#pragma unroll
    for (int o = 8; o > 0; o >>= 1)
        mx = fmaxf(mx, __shfl_xor_sync(0xffffffffu, mx, o));
    float ex = expf(v - mx);
    float se = ex;
#pragma unroll
    for (int o = 8; o > 0; o >>= 1)
        se += __shfl_xor_sync(0xffffffffu, se, o);

    if (lane < 16) {
        logits[(size_t)wid * OUTC + l16] = v;
        probs [(size_t)wid * OUTC + l16] = ex / se;
    }
}

// ---------------------------------------------------------------------------
// Launch — inputs bound by SIZE (permutation-proof).
// ---------------------------------------------------------------------------
extern "C" void kernel_launch(void* const* d_in, const int* in_sizes, int n_in,
                              void* d_out, int out_size) {
    const float* x  = nullptr;
    const int*   ei = nullptr;
    const float* ew = nullptr;
    const float* Wp[3] = {nullptr, nullptr, nullptr};
    const float* Bp[3] = {nullptr, nullptr, nullptr};
    const float* Ep[3] = {nullptr, nullptr, nullptr};
    int wi = 0, bi = 0, epi = 0;

    for (int i = 0; i < n_in; i++) {
        switch (in_sizes[i]) {
            case N_NODES * DIM: x  = (const float*)d_in[i]; break;
            case 2 * N_EDGES:   ei = (const int*)d_in[i];   break;
            case N_EDGES:       ew = (const float*)d_in[i]; break;
            case DIM * DIM:     if (wi < 2) Wp[wi++] = (const float*)d_in[i]; break;
            case DIM * OUTC:    Wp[2] = (const float*)d_in[i]; break;
            case DIM:           if (bi < 2) Bp[bi++] = (const float*)d_in[i]; break;
            case OUTC:          Bp[2] = (const float*)d_in[i]; break;
            case 1:             if (epi < 3) Ep[epi++] = (const float*)d_in[i]; break;
            default: break;
        }
    }

    float* out_logits = (float*)d_out;
    float* out_probs  = out_logits + (size_t)N_NODES * OUTC;

    uint2 *xh, *hth, *h0h;
    float4 *h1;
    int *rowptr, *wptr, *csrc;
    float *cw;
    cudaGetSymbolAddress((void**)&xh,     g_xh);
    cudaGetSymbolAddress((void**)&hth,    g_hth);
    cudaGetSymbolAddress((void**)&h0h,    g_h0h);
    cudaGetSymbolAddress((void**)&h1,     g_h1);
    cudaGetSymbolAddress((void**)&rowptr, g_rowptr);
    cudaGetSymbolAddress((void**)&wptr,   g_wptr);
    cudaGetSymbolAddress((void**)&csrc,   g_csrc);
    cudaGetSymbolAddress((void**)&cw,     g_cw);

    const int* src = ei;             // row 0
    const int* dst = ei + N_EDGES;   // row 1

    const int smem_tc = (DIM * WSTR + 32 * HSTRIDE + 64) * sizeof(float);  // ~87 KB
    cudaFuncSetAttribute(gemm_norm_tc,
                         cudaFuncAttributeMaxDynamicSharedMemorySize, smem_tc);

    const float4* x4 = (const float4*)x;
    const int ngrid  = (N_NODES * 32 + 255) / 256;   // warp-per-node grids
    const int ggrid  = N_NODES / 8;                  // 12500 (8 nodes/block)
    const int n4     = N_NODES * DIM / 4;

    // ---- CSR build (by destination), reused for all 3 layers ----
    zero_counts_kernel<<<(N_NODES + 255) / 256, 256>>>(wptr);
    hist_kernel<<<(N_EDGES + 255) / 256, 256>>>(dst, wptr);
    scan_kernel<<<1, 1024>>>(wptr, rowptr);
    fill_kernel<<<(N_EDGES + 255) / 256, 256>>>(src, dst, ew, wptr, csrc, cw);

    // ---- Layer 0 (fp16 dataflow) ----
    convert_kernel<<<1184, 256>>>(x4, xh, n4);
    gather_kernel<<<ggrid, 256>>>(xh, rowptr, csrc, cw, Ep[0], hth);
    gemm_norm_tc<<<296, 128, smem_tc>>>(hth, Wp[0], Bp[0],
                                        nullptr, (__half*)h0h, 0, 1);

    // ---- Layer 1 ----
    gather_kernel<<<ggrid, 256>>>(h0h, rowptr, csrc, cw, Ep[1], hth);
    gemm_norm_tc<<<296, 128, smem_tc>>>(hth, Wp[1], Bp[1],
                                        h1, nullptr, 1, 0);

    // ---- Layer 2: z = h1@W2, gather in 16-dim, softmax ----
    float* zbuf = (float*)xh;   // xh dead after layer-0 gather
    zmat_kernel<<<ngrid, 256>>>(h1, Wp[2], zbuf);
    final_gather_kernel<<<ngrid, 256>>>(zbuf, rowptr, csrc, Bp[2], Ep[2],
                                        out_logits, out_probs);
}